// round 6
// baseline (speedup 1.0000x reference)
#include <cuda_runtime.h>
#include <cstdint>

// Problem shape (fixed by the reference setup_inputs)
#define B_SZ   4
#define N_PTS  8192
#define M_PTS  8192

// Chamfer compute tiling
#define BLOCK  128                 // threads per block (4 warps)
#define OWN    4                   // owner pred points per thread
#define TI     (BLOCK * OWN)       // 512 pred points per block
#define TILE   256                 // target points per block (one shared tile)
#define TILE2  (TILE / 2)          // packed j-pairs
#define IC     (N_PTS / TI)        // 16 i-chunks
#define JC     (M_PTS / TILE)      // 32 j-chunks

#define FINF __int_as_float(0x7f800000)

typedef unsigned long long ull;

// Non-atomic partial-min arrays: every slot written exactly once by one block.
__device__ float gPartX[JC][B_SZ * N_PTS];   // [jc][b*N+i]: min over j-slice of 0.5*d^2
__device__ float gPartY[IC][B_SZ * M_PTS];   // [ic][b*M+j]: min over i-slice of 0.5*d^2
__device__ float gSumX;
__device__ float gSumY;
__device__ int   gCount;

// ---- packed f32x2 helpers ----
__device__ __forceinline__ ull pack2(float lo, float hi) {
    ull r;
    asm("mov.b64 %0, {%1,%2};" : "=l"(r) : "f"(lo), "f"(hi));
    return r;
}
__device__ __forceinline__ ull fma2(ull a, ull b, ull c) {
    ull d;
    asm("fma.rn.f32x2 %0, %1, %2, %3;" : "=l"(d) : "l"(a), "l"(b), "l"(c));
    return d;
}
__device__ __forceinline__ ull add2(ull a, ull b) {
    ull d;
    asm("add.rn.f32x2 %0, %1, %2;" : "=l"(d) : "l"(a), "l"(b));
    return d;
}
__device__ __forceinline__ void unpack2(ull v, float& lo, float& hi) {
    asm("mov.b64 {%0,%1}, %2;" : "=f"(lo), "=f"(hi) : "l"(v));
}

// Each unique pair (i,j) computed exactly ONCE as v = 0.5*d^2(i,j):
//   v = (0.5|t_j|^2 + 0.5|p_i|^2) - p_i . t_j    [1 add2 + 3 fma2, packed over 2 j's]
// Row mins: register accumulators -> gPartX plain store.
// Col mins: per-warp shared arrays, lane-rotated jp => lane-exclusive RMW -> gPartY.
__global__ __launch_bounds__(BLOCK) void chamfer_kernel(
    const float* __restrict__ pred, const float* __restrict__ target)
{
    // Pair-packed SoA target tile: element k holds coords of {j=2k, j=2k+1}.
    __shared__ ull sTx[TILE2], sTy[TILE2], sTz[TILE2], sTw[TILE2];
    __shared__ ull sCol[BLOCK / 32][TILE2];   // per-warp packed column mins

    const int b = blockIdx.z;
    const float* __restrict__ predB = pred   + (size_t)b * N_PTS * 3;
    const float* __restrict__ targB = target + (size_t)b * M_PTS * 3;

    const int ic = blockIdx.x;
    const int jc = blockIdx.y;
    const int Ibase = ic * TI;
    const int Jbase = jc * TILE;
    const int t = threadIdx.x;
    const int lane = t & 31;
    const int w = t >> 5;

    // init per-warp colmins to +inf
    ull inf2 = pack2(FINF, FINF);
#pragma unroll
    for (int k = t; k < (BLOCK / 32) * TILE2; k += BLOCK)
        ((ull*)sCol)[k] = inf2;

    // load target tile (x, y, z, 0.5|t|^2), pair-packed SoA
    for (int k = t; k < TILE; k += BLOCK) {
        int j = Jbase + k;
        float x = targB[3 * j + 0], y = targB[3 * j + 1], z = targB[3 * j + 2];
        ((float*)sTx)[k] = x;
        ((float*)sTy)[k] = y;
        ((float*)sTz)[k] = z;
        ((float*)sTw)[k] = 0.5f * (x * x + y * y + z * z);
    }

    // owner pred points: negated coords + half-norm, duplicated into f32x2 pairs
    ull ax[OWN], ay[OWN], az[OWN], hp[OWN];
    float rm[OWN];
#pragma unroll
    for (int p = 0; p < OWN; p++) {
        int i = Ibase + t + p * BLOCK;
        float x = predB[3 * i + 0], y = predB[3 * i + 1], z = predB[3 * i + 2];
        float h = 0.5f * (x * x + y * y + z * z);
        ax[p] = pack2(-x, -x); ay[p] = pack2(-y, -y); az[p] = pack2(-z, -z);
        hp[p] = pack2(h, h);
        rm[p] = FINF;
    }

    __syncthreads();

    ull* scol = sCol[w];

    for (int s = 0; s < TILE2; s++) {
        int jp = (s + lane) & (TILE2 - 1);   // lane-exclusive within warp each step
        ull tx = sTx[jp], ty = sTy[jp], tz = sTz[jp], tw = sTw[jp];
        float c0 = FINF, c1 = FINF;
#pragma unroll
        for (int p = 0; p < OWN; p++) {
            ull v = fma2(az[p], tz, add2(tw, hp[p]));  // 0.5(|p|^2+|t|^2) - pz*tz
            v = fma2(ay[p], ty, v);
            v = fma2(ax[p], tx, v);                     // = 0.5 * d^2
            float v0, v1;
            unpack2(v, v0, v1);
            rm[p] = fminf(rm[p], fminf(v0, v1));        // row min (over j)
            c0 = fminf(c0, v0);                          // col partial (over this thread's i's)
            c1 = fminf(c1, v1);
        }
        // fold into per-warp column min (lane-exclusive jp, no race)
        ull cc = scol[jp];
        float o0, o1;
        unpack2(cc, o0, o1);
        scol[jp] = pack2(fminf(o0, c0), fminf(o1, c1));
    }

    // row partial mins -> dedicated slice (plain store, no atomics)
    float* __restrict__ px = &gPartX[jc][b * N_PTS];
#pragma unroll
    for (int p = 0; p < OWN; p++)
        px[Ibase + t + p * BLOCK] = rm[p];

    __syncthreads();

    // column mins: combine 4 warps' arrays, one jp per thread (BLOCK == TILE2)
    {
        int jp = t;
        float m0 = FINF, m1 = FINF;
#pragma unroll
        for (int w2 = 0; w2 < BLOCK / 32; w2++) {
            float a, bb;
            unpack2(sCol[w2][jp], a, bb);
            m0 = fminf(m0, a);
            m1 = fminf(m1, bb);
        }
        float* __restrict__ py = &gPartY[ic][b * M_PTS + Jbase];
        py[2 * jp + 0] = m0;
        py[2 * jp + 1] = m1;
    }
}

// Slice-min (4 threads per point), global sum, (last block) finalize.
#define RB 256
#define XS (JC / 4)   // X slices per sub-thread (8)
#define YS (IC / 4)   // Y slices per sub-thread (4)
__global__ __launch_bounds__(RB) void reduce_fin_kernel(
    const float* __restrict__ bpp, const float* __restrict__ lamda,
    float* __restrict__ out)
{
    __shared__ float sx[RB / 32];
    __shared__ float sy[RB / 32];

    const int gid = blockIdx.x * RB + threadIdx.x;
    const int i   = gid >> 2;        // point index (covers B*N == B*M)
    const int sub = gid & 3;         // slice strip

    float mx = FINF;
#pragma unroll
    for (int k = 0; k < XS; k++)
        mx = fminf(mx, gPartX[sub * XS + k][i]);
    float my = FINF;
#pragma unroll
    for (int k = 0; k < YS; k++)
        my = fminf(my, gPartY[sub * YS + k][i]);

    // combine the 4 sub-threads of this point (lanes gid^1, gid^2 same warp)
    mx = fminf(mx, __shfl_xor_sync(0xffffffffu, mx, 1));
    mx = fminf(mx, __shfl_xor_sync(0xffffffffu, mx, 2));
    my = fminf(my, __shfl_xor_sync(0xffffffffu, my, 1));
    my = fminf(my, __shfl_xor_sync(0xffffffffu, my, 2));

    // each point's min now held by 4 lanes; d^2 = 2*m, so contribute 2m/4 = m/2
    float vx = 0.5f * mx;
    float vy = 0.5f * my;

#pragma unroll
    for (int off = 16; off > 0; off >>= 1) {
        vx += __shfl_down_sync(0xffffffffu, vx, off);
        vy += __shfl_down_sync(0xffffffffu, vy, off);
    }
    int lane = threadIdx.x & 31;
    int warp = threadIdx.x >> 5;
    if (lane == 0) { sx[warp] = vx; sy[warp] = vy; }
    __syncthreads();
    if (warp == 0) {
        vx = (lane < (RB >> 5)) ? sx[lane] : 0.0f;
        vy = (lane < (RB >> 5)) ? sy[lane] : 0.0f;
#pragma unroll
        for (int off = 16; off > 0; off >>= 1) {
            vx += __shfl_down_sync(0xffffffffu, vx, off);
            vy += __shfl_down_sync(0xffffffffu, vy, off);
        }
        if (lane == 0) {
            atomicAdd(&gSumX, vx);
            atomicAdd(&gSumY, vy);
            __threadfence();
            int ticket = atomicAdd(&gCount, 1);
            if (ticket == (int)gridDim.x - 1) {
                float sX = atomicAdd(&gSumX, 0.0f);   // all prior adds visible
                float sY = atomicAdd(&gSumY, 0.0f);
                float dist = sX * (1.0f / (B_SZ * N_PTS)) + sY * (1.0f / (B_SZ * M_PTS));
                out[0] = dist + lamda[0] * bpp[0];
                // reset accumulators for the next graph replay
                gSumX = 0.0f;
                gSumY = 0.0f;
                __threadfence();
                gCount = 0;
            }
        }
    }
}

extern "C" void kernel_launch(void* const* d_in, const int* in_sizes, int n_in,
                              void* d_out, int out_size)
{
    const float* pred   = (const float*)d_in[0];
    const float* target = (const float*)d_in[1];
    const float* bpp    = (const float*)d_in[2];
    const float* lamda  = (const float*)d_in[3];
    float* out = (float*)d_out;

    // 1) single-pass chamfer: each pair once as 0.5*d^2; partial mins to
    //    dedicated slices (no init kernel, no global atomics)
    dim3 grid(IC, JC, B_SZ);   // (16, 32, 4) = 2048 blocks
    chamfer_kernel<<<grid, BLOCK>>>(pred, target);

    // 2) 4-way-parallel slice-min + global sum + fused finalize
    reduce_fin_kernel<<<(B_SZ * N_PTS * 4) / RB, RB>>>(bpp, lamda, out);
}

// round 7
// speedup vs baseline: 1.0639x; 1.0639x over previous
#include <cuda_runtime.h>
#include <cstdint>

// Problem shape (fixed by the reference setup_inputs)
#define B_SZ   4
#define N_PTS  8192
#define M_PTS  8192

// Chamfer compute tiling (R5 config: best measured)
#define BLOCK  128                 // threads per block (4 warps)
#define OWN    8                   // owner pred points per thread
#define TI     (BLOCK * OWN)       // 1024 pred points per block
#define TILE   256                 // target points per block (one shared tile)
#define TILE2  (TILE / 2)          // packed j-pairs
#define IC     (N_PTS / TI)        // 8  i-chunks
#define JC     (M_PTS / TILE)      // 32 j-chunks
#define TOTAL  (IC * JC * B_SZ)    // 1024 blocks
#define RWORK  256                 // last-finishing blocks that do the reduction
#define NPTS_T (B_SZ * N_PTS)      // 32768 (== B_SZ * M_PTS)

#define FINF __int_as_float(0x7f800000)

typedef unsigned long long ull;

// Non-atomic partial-min arrays: every slot written exactly once by one block.
__device__ float gPartX[JC][NPTS_T];   // [jc][b*N+i]: min over j-slice of 0.5*d^2
__device__ float gPartY[IC][NPTS_T];   // [ic][b*M+j]: min over i-slice of 0.5*d^2
__device__ float gSumX;
__device__ float gSumY;
__device__ int   gDone;   // chamfer completion ticket
__device__ int   gRed;    // reduction completion ticket

// ---- packed f32x2 helpers ----
__device__ __forceinline__ ull pack2(float lo, float hi) {
    ull r;
    asm("mov.b64 %0, {%1,%2};" : "=l"(r) : "f"(lo), "f"(hi));
    return r;
}
__device__ __forceinline__ ull fma2(ull a, ull b, ull c) {
    ull d;
    asm("fma.rn.f32x2 %0, %1, %2, %3;" : "=l"(d) : "l"(a), "l"(b), "l"(c));
    return d;
}
__device__ __forceinline__ ull add2(ull a, ull b) {
    ull d;
    asm("add.rn.f32x2 %0, %1, %2;" : "=l"(d) : "l"(a), "l"(b));
    return d;
}
__device__ __forceinline__ void unpack2(ull v, float& lo, float& hi) {
    asm("mov.b64 {%0,%1}, %2;" : "=f"(lo), "=f"(hi) : "l"(v));
}

// Single fused kernel:
//  Phase 1 (all 1024 blocks): each unique pair (i,j) once as v = 0.5*d^2(i,j).
//    Row mins -> register accumulators -> gPartX (plain stores, no atomics).
//    Col mins -> per-warp shared arrays (lane-rotated, race-free) -> gPartY.
//  Phase 2 (last RWORK blocks by completion ticket): spin until all partials
//    written, then slice-min + global sum + finalize. No second launch.
__global__ __launch_bounds__(BLOCK) void chamfer_fused_kernel(
    const float* __restrict__ pred, const float* __restrict__ target,
    const float* __restrict__ bpp, const float* __restrict__ lamda,
    float* __restrict__ out)
{
    // Pair-packed SoA target tile: element k holds coords of {j=2k, j=2k+1}.
    __shared__ ull sTx[TILE2], sTy[TILE2], sTz[TILE2], sTw[TILE2];
    __shared__ ull sCol[BLOCK / 32][TILE2];   // per-warp packed column mins
    __shared__ int sTicket;
    __shared__ float sx[BLOCK / 32], sy[BLOCK / 32];

    const int b  = blockIdx.z;
    const float* __restrict__ predB = pred   + (size_t)b * N_PTS * 3;
    const float* __restrict__ targB = target + (size_t)b * M_PTS * 3;

    const int ic = blockIdx.x;
    const int jc = blockIdx.y;
    const int Ibase = ic * TI;
    const int Jbase = jc * TILE;
    const int t = threadIdx.x;
    const int lane = t & 31;
    const int w = t >> 5;

    // init per-warp colmins to +inf
    ull inf2 = pack2(FINF, FINF);
#pragma unroll
    for (int k = t; k < (BLOCK / 32) * TILE2; k += BLOCK)
        ((ull*)sCol)[k] = inf2;

    // load target tile (x, y, z, 0.5|t|^2), pair-packed SoA
    for (int k = t; k < TILE; k += BLOCK) {
        int j = Jbase + k;
        float x = targB[3 * j + 0], y = targB[3 * j + 1], z = targB[3 * j + 2];
        ((float*)sTx)[k] = x;
        ((float*)sTy)[k] = y;
        ((float*)sTz)[k] = z;
        ((float*)sTw)[k] = 0.5f * (x * x + y * y + z * z);
    }

    // owner pred points: negated coords + half-norm, duplicated into f32x2 pairs
    ull ax[OWN], ay[OWN], az[OWN], hp[OWN];
    float rm[OWN];
#pragma unroll
    for (int p = 0; p < OWN; p++) {
        int i = Ibase + t + p * BLOCK;
        float x = predB[3 * i + 0], y = predB[3 * i + 1], z = predB[3 * i + 2];
        float h = 0.5f * (x * x + y * y + z * z);
        ax[p] = pack2(-x, -x); ay[p] = pack2(-y, -y); az[p] = pack2(-z, -z);
        hp[p] = pack2(h, h);
        rm[p] = FINF;
    }

    __syncthreads();

    ull* scol = sCol[w];

    for (int s = 0; s < TILE2; s++) {
        int jp = (s + lane) & (TILE2 - 1);   // lane-exclusive within warp each step
        ull tx = sTx[jp], ty = sTy[jp], tz = sTz[jp], tw = sTw[jp];
        float c0 = FINF, c1 = FINF;
#pragma unroll
        for (int p = 0; p < OWN; p++) {
            ull v = fma2(az[p], tz, add2(tw, hp[p]));  // 0.5(|p|^2+|t|^2) - pz*tz
            v = fma2(ay[p], ty, v);
            v = fma2(ax[p], tx, v);                     // = 0.5 * d^2
            float v0, v1;
            unpack2(v, v0, v1);
            rm[p] = fminf(rm[p], fminf(v0, v1));        // row min (over j)
            c0 = fminf(c0, v0);                          // col partial
            c1 = fminf(c1, v1);
        }
        // fold into per-warp column min (lane-exclusive jp, no race)
        ull cc = scol[jp];
        float o0, o1;
        unpack2(cc, o0, o1);
        scol[jp] = pack2(fminf(o0, c0), fminf(o1, c1));
    }

    // row partial mins -> dedicated slice (plain store, no atomics)
    float* __restrict__ px = &gPartX[jc][b * N_PTS];
#pragma unroll
    for (int p = 0; p < OWN; p++)
        px[Ibase + t + p * BLOCK] = rm[p];

    __syncthreads();

    // column mins: combine 4 warps' arrays, one jp per thread (BLOCK == TILE2)
    {
        int jp = t;
        float m0 = FINF, m1 = FINF;
#pragma unroll
        for (int w2 = 0; w2 < BLOCK / 32; w2++) {
            float a, bb;
            unpack2(sCol[w2][jp], a, bb);
            m0 = fminf(m0, a);
            m1 = fminf(m1, bb);
        }
        float* __restrict__ py = &gPartY[ic][b * M_PTS + Jbase];
        py[2 * jp + 0] = m0;
        py[2 * jp + 1] = m1;
    }

    // ---- Phase 2 gate: completion ticket ----
    __threadfence();   // make this block's partial stores globally visible
    if (t == 0) sTicket = atomicAdd(&gDone, 1);
    __syncthreads();
    const int ticket = sTicket;
    if (ticket < TOTAL - RWORK) return;   // early finishers exit, free SM slots

    // last RWORK finishers: wait for all partials (deadlock-safe: spinners <= RWORK
    // << resident capacity; exited blocks free slots for remaining waves)
    if (t == 0) {
        while (*(volatile int*)&gDone < TOTAL) __nanosleep(64);
    }
    __syncthreads();
    __threadfence();   // order our reads after the observed completion

    // slice reduction: 128 points per reducer block, one per thread
    const int rb = ticket - (TOTAL - RWORK);       // 0..RWORK-1
    const int i  = rb * BLOCK + t;                 // 0..NPTS_T-1

    float mx = FINF;
#pragma unroll 8
    for (int k = 0; k < JC; k++)
        mx = fminf(mx, gPartX[k][i]);
    float my = FINF;
#pragma unroll 8
    for (int k = 0; k < IC; k++)
        my = fminf(my, gPartY[k][i]);

    float vx = 2.0f * mx;   // d^2 = 2 * (0.5 d^2)
    float vy = 2.0f * my;

#pragma unroll
    for (int off = 16; off > 0; off >>= 1) {
        vx += __shfl_down_sync(0xffffffffu, vx, off);
        vy += __shfl_down_sync(0xffffffffu, vy, off);
    }
    if (lane == 0) { sx[w] = vx; sy[w] = vy; }
    __syncthreads();
    if (w == 0) {
        vx = (lane < (BLOCK >> 5)) ? sx[lane] : 0.0f;
        vy = (lane < (BLOCK >> 5)) ? sy[lane] : 0.0f;
#pragma unroll
        for (int off = 2; off > 0; off >>= 1) {
            vx += __shfl_down_sync(0xffffffffu, vx, off);
            vy += __shfl_down_sync(0xffffffffu, vy, off);
        }
        if (lane == 0) {
            atomicAdd(&gSumX, vx);
            atomicAdd(&gSumY, vy);
            __threadfence();
            int rt = atomicAdd(&gRed, 1);
            if (rt == RWORK - 1) {
                float sX = atomicAdd(&gSumX, 0.0f);   // all prior adds visible
                float sY = atomicAdd(&gSumY, 0.0f);
                float dist = sX * (1.0f / (B_SZ * N_PTS)) + sY * (1.0f / (B_SZ * M_PTS));
                out[0] = dist + lamda[0] * bpp[0];
                // reset for the next graph replay
                gSumX = 0.0f;
                gSumY = 0.0f;
                gDone = 0;
                __threadfence();
                gRed = 0;
            }
        }
    }
}

extern "C" void kernel_launch(void* const* d_in, const int* in_sizes, int n_in,
                              void* d_out, int out_size)
{
    const float* pred   = (const float*)d_in[0];
    const float* target = (const float*)d_in[1];
    const float* bpp    = (const float*)d_in[2];
    const float* lamda  = (const float*)d_in[3];
    float* out = (float*)d_out;

    // Single fused launch: chamfer + ticket-gated reduction + finalize
    dim3 grid(IC, JC, B_SZ);   // (8, 32, 4) = 1024 blocks
    chamfer_fused_kernel<<<grid, BLOCK>>>(pred, target, bpp, lamda, out);
}

// round 8
// speedup vs baseline: 1.0765x; 1.0118x over previous
#include <cuda_runtime.h>
#include <cstdint>

// Problem shape (fixed by the reference setup_inputs)
#define B_SZ   4
#define N_PTS  8192
#define M_PTS  8192

// Chamfer compute tiling (R5 config: best measured)
#define BLOCK  128                 // threads per block (4 warps)
#define OWN    8                   // owner pred points per thread
#define TI     (BLOCK * OWN)       // 1024 pred points per block
#define TILE   256                 // target points per block (one shared tile)
#define TILE2  (TILE / 2)          // packed j-pairs
#define IC     (N_PTS / TI)        // 8  i-chunks
#define JC     (M_PTS / TILE)      // 32 j-chunks
#define TOTAL  (IC * JC * B_SZ)    // 1024 blocks
#define RWORK  512                 // last-finishing blocks that do the reduction
#define NPTS_T (B_SZ * N_PTS)      // 32768 (== B_SZ * M_PTS)
#define PPB    (NPTS_T / RWORK)    // 64 points per reducer block

#define FINF __int_as_float(0x7f800000)

typedef unsigned long long ull;

// Non-atomic partial-min arrays: every slot written exactly once by one block.
__device__ float gPartX[JC][NPTS_T];   // [jc][b*N+i]: min over j-slice of 0.5*d^2
__device__ float gPartY[IC][NPTS_T];   // [ic][b*M+j]: min over i-slice of 0.5*d^2
__device__ float gSumX;
__device__ float gSumY;
__device__ int   gDone;   // chamfer completion ticket
__device__ int   gRed;    // reduction completion ticket

// ---- packed f32x2 helpers ----
__device__ __forceinline__ ull pack2(float lo, float hi) {
    ull r;
    asm("mov.b64 %0, {%1,%2};" : "=l"(r) : "f"(lo), "f"(hi));
    return r;
}
__device__ __forceinline__ ull fma2(ull a, ull b, ull c) {
    ull d;
    asm("fma.rn.f32x2 %0, %1, %2, %3;" : "=l"(d) : "l"(a), "l"(b), "l"(c));
    return d;
}
__device__ __forceinline__ ull add2(ull a, ull b) {
    ull d;
    asm("add.rn.f32x2 %0, %1, %2;" : "=l"(d) : "l"(a), "l"(b));
    return d;
}
__device__ __forceinline__ void unpack2(ull v, float& lo, float& hi) {
    asm("mov.b64 {%0,%1}, %2;" : "=f"(lo), "=f"(hi) : "l"(v));
}

// Single fused kernel:
//  Phase 1 (all 1024 blocks): each unique pair (i,j) once as v = 0.5*d^2(i,j).
//    Row mins -> register accumulators -> gPartX (plain stores, no atomics).
//    Col mins -> per-warp shared arrays (lane-rotated, race-free) -> gPartY.
//  Phase 2 (last RWORK finishers by ticket): spin until all partials written,
//    then slice-min (2 threads/point) + global sum + finalize. No 2nd launch.
__global__ __launch_bounds__(BLOCK, 7) void chamfer_fused_kernel(
    const float* __restrict__ pred, const float* __restrict__ target,
    const float* __restrict__ bpp, const float* __restrict__ lamda,
    float* __restrict__ out)
{
    // Pair-packed SoA target tile: element k holds coords of {j=2k, j=2k+1}.
    __shared__ ull sTx[TILE2], sTy[TILE2], sTz[TILE2], sTw[TILE2];
    __shared__ ull sCol[BLOCK / 32][TILE2];   // per-warp packed column mins
    __shared__ int sTicket;
    __shared__ float sx[BLOCK / 32], sy[BLOCK / 32];

    const int b  = blockIdx.z;
    const float* __restrict__ predB = pred   + (size_t)b * N_PTS * 3;
    const float* __restrict__ targB = target + (size_t)b * M_PTS * 3;

    const int ic = blockIdx.x;
    const int jc = blockIdx.y;
    const int Ibase = ic * TI;
    const int Jbase = jc * TILE;
    const int t = threadIdx.x;
    const int lane = t & 31;
    const int w = t >> 5;

    // init per-warp colmins to +inf
    ull inf2 = pack2(FINF, FINF);
#pragma unroll
    for (int k = t; k < (BLOCK / 32) * TILE2; k += BLOCK)
        ((ull*)sCol)[k] = inf2;

    // load target tile (x, y, z, 0.5|t|^2), pair-packed SoA
    for (int k = t; k < TILE; k += BLOCK) {
        int j = Jbase + k;
        float x = targB[3 * j + 0], y = targB[3 * j + 1], z = targB[3 * j + 2];
        ((float*)sTx)[k] = x;
        ((float*)sTy)[k] = y;
        ((float*)sTz)[k] = z;
        ((float*)sTw)[k] = 0.5f * (x * x + y * y + z * z);
    }

    // owner pred points: negated coords + half-norm, duplicated into f32x2 pairs
    ull ax[OWN], ay[OWN], az[OWN], hp[OWN];
    float rm[OWN];
#pragma unroll
    for (int p = 0; p < OWN; p++) {
        int i = Ibase + t + p * BLOCK;
        float x = predB[3 * i + 0], y = predB[3 * i + 1], z = predB[3 * i + 2];
        float h = 0.5f * (x * x + y * y + z * z);
        ax[p] = pack2(-x, -x); ay[p] = pack2(-y, -y); az[p] = pack2(-z, -z);
        hp[p] = pack2(h, h);
        rm[p] = FINF;
    }

    __syncthreads();

    ull* scol = sCol[w];

    for (int s = 0; s < TILE2; s++) {
        int jp = (s + lane) & (TILE2 - 1);   // lane-exclusive within warp each step
        ull tx = sTx[jp], ty = sTy[jp], tz = sTz[jp], tw = sTw[jp];
        float c0 = FINF, c1 = FINF;
#pragma unroll
        for (int p = 0; p < OWN; p++) {
            ull v = fma2(az[p], tz, add2(tw, hp[p]));  // 0.5(|p|^2+|t|^2) - pz*tz
            v = fma2(ay[p], ty, v);
            v = fma2(ax[p], tx, v);                     // = 0.5 * d^2
            float v0, v1;
            unpack2(v, v0, v1);
            rm[p] = fminf(rm[p], fminf(v0, v1));        // row min (over j)
            c0 = fminf(c0, v0);                          // col partial
            c1 = fminf(c1, v1);
        }
        // fold into per-warp column min (lane-exclusive jp, no race)
        ull cc = scol[jp];
        float o0, o1;
        unpack2(cc, o0, o1);
        scol[jp] = pack2(fminf(o0, c0), fminf(o1, c1));
    }

    // row partial mins -> dedicated slice (plain store, no atomics)
    float* __restrict__ px = &gPartX[jc][b * N_PTS];
#pragma unroll
    for (int p = 0; p < OWN; p++)
        px[Ibase + t + p * BLOCK] = rm[p];

    __syncthreads();

    // column mins: combine 4 warps' arrays, one jp per thread (BLOCK == TILE2)
    {
        int jp = t;
        float m0 = FINF, m1 = FINF;
#pragma unroll
        for (int w2 = 0; w2 < BLOCK / 32; w2++) {
            float a, bb;
            unpack2(sCol[w2][jp], a, bb);
            m0 = fminf(m0, a);
            m1 = fminf(m1, bb);
        }
        float* __restrict__ py = &gPartY[ic][b * M_PTS + Jbase];
        py[2 * jp + 0] = m0;
        py[2 * jp + 1] = m1;
    }

    // ---- Phase 2 gate: completion ticket ----
    __threadfence();   // make this block's partial stores globally visible
    if (t == 0) sTicket = atomicAdd(&gDone, 1);
    __syncthreads();
    const int ticket = sTicket;
    if (ticket < TOTAL - RWORK) return;   // early finishers exit, free SM slots

    // last RWORK finishers: wait for all partials (deadlock-safe: RWORK=512 <=
    // guaranteed-resident capacity; launch_bounds pins 7 blocks/SM => single wave)
    if (t == 0) {
        while (*(volatile int*)&gDone < TOTAL) __nanosleep(32);
    }
    __syncthreads();
    __threadfence();   // order our reads after the observed completion

    // slice reduction: 64 points per reducer block, 2 threads per point
    const int rb  = ticket - (TOTAL - RWORK);      // 0..RWORK-1
    const int i   = rb * PPB + (t >> 1);           // point index
    const int sub = t & 1;                          // slice strip

    float mx = FINF;
#pragma unroll
    for (int k = 0; k < JC / 2; k++)
        mx = fminf(mx, gPartX[sub * (JC / 2) + k][i]);
    float my = FINF;
#pragma unroll
    for (int k = 0; k < IC / 2; k++)
        my = fminf(my, gPartY[sub * (IC / 2) + k][i]);

    // combine the 2 sub-threads of this point (adjacent lanes, same warp)
    mx = fminf(mx, __shfl_xor_sync(0xffffffffu, mx, 1));
    my = fminf(my, __shfl_xor_sync(0xffffffffu, my, 1));

    // d^2 = 2*m; 2 lanes hold each point's min -> contribute 2m/2 = m each
    float vx = mx;
    float vy = my;

#pragma unroll
    for (int off = 16; off > 0; off >>= 1) {
        vx += __shfl_down_sync(0xffffffffu, vx, off);
        vy += __shfl_down_sync(0xffffffffu, vy, off);
    }
    if (lane == 0) { sx[w] = vx; sy[w] = vy; }
    __syncthreads();
    if (w == 0) {
        vx = (lane < (BLOCK >> 5)) ? sx[lane] : 0.0f;
        vy = (lane < (BLOCK >> 5)) ? sy[lane] : 0.0f;
#pragma unroll
        for (int off = 2; off > 0; off >>= 1) {
            vx += __shfl_down_sync(0xffffffffu, vx, off);
            vy += __shfl_down_sync(0xffffffffu, vy, off);
        }
        if (lane == 0) {
            atomicAdd(&gSumX, vx);
            atomicAdd(&gSumY, vy);
            __threadfence();
            int rt = atomicAdd(&gRed, 1);
            if (rt == RWORK - 1) {
                float sX = atomicAdd(&gSumX, 0.0f);   // all prior adds visible
                float sY = atomicAdd(&gSumY, 0.0f);
                float dist = sX * (1.0f / (B_SZ * N_PTS)) + sY * (1.0f / (B_SZ * M_PTS));
                out[0] = dist + lamda[0] * bpp[0];
                // reset for the next graph replay
                gSumX = 0.0f;
                gSumY = 0.0f;
                gDone = 0;
                __threadfence();
                gRed = 0;
            }
        }
    }
}

extern "C" void kernel_launch(void* const* d_in, const int* in_sizes, int n_in,
                              void* d_out, int out_size)
{
    const float* pred   = (const float*)d_in[0];
    const float* target = (const float*)d_in[1];
    const float* bpp    = (const float*)d_in[2];
    const float* lamda  = (const float*)d_in[3];
    float* out = (float*)d_out;

    // Single fused launch: chamfer + ticket-gated wide reduction + finalize
    dim3 grid(IC, JC, B_SZ);   // (8, 32, 4) = 1024 blocks
    chamfer_fused_kernel<<<grid, BLOCK>>>(pred, target, bpp, lamda, out);
}